// round 14
// baseline (speedup 1.0000x reference)
#include <cuda_runtime.h>
#include <math.h>
#include <stdint.h>

// Problem constants
#define B_    8
#define NE    4
#define Tn    1024
#define D_    1024
#define G_    8
#define BLK   128
#define TT    64
#define DLLM  2048
#define NT    (B_*NE*Tn)          // 32768 tokens
#define SCALEF 0.08838834764831845f  // 128^-0.5

// -------- device scratch (static, no dynamic allocation) --------
__device__ float g_kvp[8*2*8*64*128];    // K-slice partials
__device__ float g_k[B_*TT*BLK];         // [8][64][128]
__device__ float g_v[B_*TT*BLK];
__device__ float g_A[NT*BLK];            // gate*gamma
__device__ float g_B[NT*BLK];            // gate*beta

__device__ __forceinline__ uint32_t f2tf32(float x) {
    uint32_t u;
    asm("cvt.rna.tf32.f32 %0, %1;" : "=r"(u) : "f"(x));
    return u;
}

__device__ __forceinline__ void cp16(void* dst_smem, const void* src_gmem) {
    uint32_t d = (uint32_t)__cvta_generic_to_shared(dst_smem);
    asm volatile("cp.async.cg.shared.global [%0], [%1], 16;" :: "r"(d), "l"(src_gmem));
}

#define MMA_TF32(acc, a0,a1,a2,a3, b0,b1) \
    asm volatile( \
        "mma.sync.aligned.m16n8k8.row.col.f32.tf32.tf32.f32 " \
        "{%0,%1,%2,%3}, {%4,%5,%6,%7}, {%8,%9}, {%0,%1,%2,%3};" \
        : "+f"(acc[0]), "+f"(acc[1]), "+f"(acc[2]), "+f"(acc[3]) \
        : "r"(a0), "r"(a1), "r"(a2), "r"(a3), "r"(b0), "r"(b1))

// Stage a 128x128 row-major fp32 weight into MMA-fragment-packed tf32 layout:
//   P[((n>>3)*16 + (k>>3))*64 + (n&7)*8 + (k&3)*2 + ((k>>2)&1)]
// B-fragment (ntile nt, kstep ks) for thread (gid,ctg) is then the uint2 at
//   P + ((nt*16+ks)*64 + gid*8 + ctg*2)            -> one LDS.64.
__device__ __forceinline__ void stage_weight_packed(uint32_t* P, const float* W, int tid) {
    const float4* wsrc = (const float4*)W;
    #pragma unroll 4
    for (int i4 = tid; i4 < 4096; i4 += 256) {
        float4 v = wsrc[i4];
        int idx = i4 * 4;
        int n = idx >> 7, k = idx & 127;          // k aligned to 4
        int base = ((n >> 3)*16 + (k >> 3))*64 + (n & 7)*8 + ((k >> 2) & 1);
        P[base + 0] = f2tf32(v.x);
        P[base + 2] = f2tf32(v.y);
        P[base + 4] = f2tf32(v.z);
        P[base + 6] = f2tf32(v.w);
    }
}

#define BFRAG(P, nt, ks) (*(const uint2*)&(P)[(((nt)*16 + (ks))*64) + gid*8 + ctg*2])

// ============================================================================
// Kernel 1: kv3 — split-K tf32 MMA k/v projection (unchanged, proven).
// ============================================================================
#define KV3_SMEM (2 * (64 + 128) * 68 * 4)

__global__ void __launch_bounds__(256)
kv3_kernel(const float* __restrict__ h_llm,
           const float* __restrict__ Wk,
           const float* __restrict__ Wv) {
    extern __shared__ float sm[];
    float* ab[2] = { sm,                sm + 64*68 };
    float* wb[2] = { sm + 2*64*68,      sm + 2*64*68 + 128*68 };

    int tid = threadIdx.x;
    int bid = blockIdx.x;
    int slice = bid >> 4;
    int b     = (bid >> 1) & 7;
    int which = bid & 1;
    const float* W    = which ? Wv : Wk;
    const float* hsrc = h_llm + (size_t)b * TT * DLLM + slice * 256;
    const float* wsrc = W + slice * 256;

    auto issue = [&](int ch, int bi) {
        const float* as = hsrc + ch * 64;
        const float* bs = wsrc + ch * 64;
        #pragma unroll
        for (int i = tid; i < 1024; i += 256) {
            int r = i >> 4, q = i & 15;
            cp16(&ab[bi][r*68 + q*4], as + (size_t)r*DLLM + q*4);
        }
        #pragma unroll
        for (int i = tid; i < 2048; i += 256) {
            int r = i >> 4, q = i & 15;
            cp16(&wb[bi][r*68 + q*4], bs + (size_t)r*DLLM + q*4);
        }
        asm volatile("cp.async.commit_group;");
    };

    issue(0, 0);
    issue(1, 1);

    int w = tid >> 5, lane = tid & 31;
    int gid = lane >> 2, ctg = lane & 3;
    int row0 = (w & 3) * 16;
    int col0 = (w >> 2) * 64;

    float acc[8][4];
    #pragma unroll
    for (int ni = 0; ni < 8; ni++)
        #pragma unroll
        for (int j = 0; j < 4; j++) acc[ni][j] = 0.f;

    #pragma unroll
    for (int ch = 0; ch < 4; ch++) {
        if (ch == 3) asm volatile("cp.async.wait_group 0;");
        else         asm volatile("cp.async.wait_group 1;");
        __syncthreads();
        const float* A  = ab[ch & 1];
        const float* Wf = wb[ch & 1];

        #pragma unroll
        for (int ks = 0; ks < 8; ks++) {
            int k0 = ks * 8;
            const float* rp = A + (row0 + gid)*68 + k0 + ctg;
            uint32_t a0 = f2tf32(rp[0]);
            uint32_t a1 = f2tf32(rp[8*68]);
            uint32_t a2 = f2tf32(rp[4]);
            uint32_t a3 = f2tf32(rp[8*68 + 4]);
            #pragma unroll
            for (int ni = 0; ni < 8; ni++) {
                const float* np = Wf + (col0 + ni*8 + gid)*68 + k0 + ctg;
                uint32_t b0 = f2tf32(np[0]);
                uint32_t b1 = f2tf32(np[4]);
                MMA_TF32(acc[ni], a0, a1, a2, a3, b0, b1);
            }
        }
        __syncthreads();
        if (ch + 2 < 4) issue(ch + 2, ch & 1);
    }

    float* outp = g_kvp + ((size_t)(slice*2 + which)*8 + b) * 8192;
    #pragma unroll
    for (int ni = 0; ni < 8; ni++) {
        int o = col0 + ni*8 + ctg*2;
        int s1 = row0 + gid;
        *(float2*)&outp[s1*128 + o]     = make_float2(acc[ni][0], acc[ni][1]);
        *(float2*)&outp[(s1+8)*128 + o] = make_float2(acc[ni][2], acc[ni][3]);
    }
}

__global__ void kv_reduce(const float* __restrict__ bk,
                          const float* __restrict__ bv) {
    int idx = blockIdx.x * 256 + threadIdx.x;
    if (idx >= 2*8*64*128/4) return;
    int which = idx >> 14;
    int rem   = idx & 16383;
    int o4 = rem & 31;
    const float* bias = which ? bv : bk;
    float4 s = *(const float4*)&bias[o4*4];
    #pragma unroll
    for (int sl = 0; sl < 8; sl++) {
        const float4* p = (const float4*)(g_kvp + (size_t)(sl*2 + which)*65536) + rem;
        float4 v = *p;
        s.x += v.x; s.y += v.y; s.z += v.z; s.w += v.w;
    }
    float* dst = which ? g_v : g_k;
    *((float4*)dst + rem) = s;
}

// ============================================================================
// Kernel 2: mega2 — fused maxpool -> q -> attention -> gamma/beta.
// Weight GEMMs (Wq/Wg/Wb) now use fragment-packed tf32 layout (LDS.64 B-frags).
// ============================================================================
#define M2_SMEM (25600 * 4)

__global__ void __launch_bounds__(256)
mega2_kernel(const float* __restrict__ h_prime,
             const float* __restrict__ Wq, const float* __restrict__ bq,
             const float* __restrict__ Wg, const float* __restrict__ bg,
             const float* __restrict__ Wb, const float* __restrict__ bb) {
    extern __shared__ float smf[];
    float* R1 = smf;                 // 17152 floats
    float* R2 = smf + 17152;         // 8448: inv -> q -> ctx, stride 132
    uint32_t* ws = (uint32_t*)R1;    // packed weight [16384 words]
    float* kbuf = R1;                // k [64][132]
    float* vbuf = R1 + 8448;         // vT [128][68]
    float* ss   = R1;                // scores [64][68]

    int tid = threadIdx.x;
    size_t t0 = (size_t)blockIdx.x * 64;
    int b = (int)(t0 >> 12);

    int w = tid >> 5, lane = tid & 31;
    int gid = lane >> 2, ctg = lane & 3;
    int row0  = (w & 3) * 16;
    int col0  = (w >> 2) * 64;
    int nt0   = (w >> 2) * 8;        // first n-tile for N=128 phases
    int col0s = (w >> 2) * 32;

    // ---- P0: stage Wq packed + maxpool inv -> R2 ----
    stage_weight_packed(ws, Wq, tid);
    #pragma unroll 2
    for (int i4 = tid; i4 < 2048; i4 += 256) {
        int t = i4 >> 5, d4 = i4 & 31;
        const float4* hp = (const float4*)(h_prime + (t0 + t)*1024 + d4*4);
        float4 m = hp[0];
        #pragma unroll
        for (int g = 1; g < 8; g++) {
            float4 x = hp[g*32];
            m.x = fmaxf(m.x, x.x); m.y = fmaxf(m.y, x.y);
            m.z = fmaxf(m.z, x.z); m.w = fmaxf(m.w, x.w);
        }
        *(float4*)&R2[t*132 + d4*4] = m;
    }
    __syncthreads();

    // ---- P1: q = inv @ WqT ----
    float qacc[8][4];
    #pragma unroll
    for (int ni = 0; ni < 8; ni++)
        #pragma unroll
        for (int j = 0; j < 4; j++) qacc[ni][j] = 0.f;
    #pragma unroll
    for (int ks = 0; ks < 16; ks++) {
        int k0 = ks * 8;
        const float* rp = R2 + (row0 + gid)*132 + k0 + ctg;
        uint32_t a0 = f2tf32(rp[0]);
        uint32_t a1 = f2tf32(rp[8*132]);
        uint32_t a2 = f2tf32(rp[4]);
        uint32_t a3 = f2tf32(rp[8*132 + 4]);
        #pragma unroll
        for (int ni = 0; ni < 8; ni++) {
            uint2 b2 = BFRAG(ws, nt0 + ni, ks);
            MMA_TF32(qacc[ni], a0, a1, a2, a3, b2.x, b2.y);
        }
    }
    __syncthreads();

    // ---- P2: write q (scaled+biased) over inv; load k + vT ----
    #pragma unroll
    for (int ni = 0; ni < 8; ni++) {
        int c = col0 + ni*8 + ctg*2;
        float2 b2 = *(const float2*)&bq[c];
        int r1 = row0 + gid;
        R2[r1*132 + c]     = (qacc[ni][0] + b2.x) * SCALEF;
        R2[r1*132 + c + 1] = (qacc[ni][1] + b2.y) * SCALEF;
        R2[(r1+8)*132 + c]     = (qacc[ni][2] + b2.x) * SCALEF;
        R2[(r1+8)*132 + c + 1] = (qacc[ni][3] + b2.y) * SCALEF;
    }
    for (int i4 = tid; i4 < 2048; i4 += 256) {
        int s = i4 >> 5, d4 = i4 & 31;
        *(float4*)&kbuf[s*132 + d4*4] = *(const float4*)&g_k[(size_t)b*8192 + s*128 + d4*4];
    }
    for (int idx = tid; idx < 8192; idx += 256) {
        int s = idx >> 7, d = idx & 127;
        vbuf[d*68 + s] = g_v[(size_t)b*8192 + idx];
    }
    __syncthreads();

    // ---- P3: scores = q @ kT ----
    float sacc[4][4];
    #pragma unroll
    for (int ni = 0; ni < 4; ni++)
        #pragma unroll
        for (int j = 0; j < 4; j++) sacc[ni][j] = 0.f;
    #pragma unroll
    for (int ks = 0; ks < 16; ks++) {
        int k0 = ks * 8;
        const float* rp = R2 + (row0 + gid)*132 + k0 + ctg;
        uint32_t a0 = f2tf32(rp[0]);
        uint32_t a1 = f2tf32(rp[8*132]);
        uint32_t a2 = f2tf32(rp[4]);
        uint32_t a3 = f2tf32(rp[8*132 + 4]);
        #pragma unroll
        for (int ni = 0; ni < 4; ni++) {
            const float* np = kbuf + (col0s + ni*8 + gid)*132 + k0 + ctg;
            uint32_t b0 = f2tf32(np[0]);
            uint32_t b1 = f2tf32(np[4]);
            MMA_TF32(sacc[ni], a0, a1, a2, a3, b0, b1);
        }
    }
    __syncthreads();

    // ---- P4: write scores (stride 68) ----
    #pragma unroll
    for (int ni = 0; ni < 4; ni++) {
        int c = col0s + ni*8 + ctg*2;
        int r1 = row0 + gid;
        ss[r1*68 + c]     = sacc[ni][0];
        ss[r1*68 + c + 1] = sacc[ni][1];
        ss[(r1+8)*68 + c]     = sacc[ni][2];
        ss[(r1+8)*68 + c + 1] = sacc[ni][3];
    }
    __syncthreads();

    // ---- P5: softmax ----
    if (tid < 64) {
        float* row = ss + tid*68;
        float m = row[0];
        #pragma unroll 8
        for (int s = 1; s < 64; s++) m = fmaxf(m, row[s]);
        float sum = 0.f;
        #pragma unroll 8
        for (int s = 0; s < 64; s++) { float e = __expf(row[s] - m); row[s] = e; sum += e; }
        float inv = 1.f / sum;
        #pragma unroll 8
        for (int s = 0; s < 64; s++) row[s] *= inv;
    }
    __syncthreads();

    // ---- P6: ctx = attn @ v ----
    float cacc[8][4];
    #pragma unroll
    for (int ni = 0; ni < 8; ni++)
        #pragma unroll
        for (int j = 0; j < 4; j++) cacc[ni][j] = 0.f;
    #pragma unroll
    for (int ks = 0; ks < 8; ks++) {
        int k0 = ks * 8;
        const float* rp = ss + (row0 + gid)*68 + k0 + ctg;
        uint32_t a0 = f2tf32(rp[0]);
        uint32_t a1 = f2tf32(rp[8*68]);
        uint32_t a2 = f2tf32(rp[4]);
        uint32_t a3 = f2tf32(rp[8*68 + 4]);
        #pragma unroll
        for (int ni = 0; ni < 8; ni++) {
            const float* np = vbuf + (col0 + ni*8 + gid)*68 + k0 + ctg;
            uint32_t b0 = f2tf32(np[0]);
            uint32_t b1 = f2tf32(np[4]);
            MMA_TF32(cacc[ni], a0, a1, a2, a3, b0, b1);
        }
    }
    __syncthreads();

    // ---- P7: write ctx over q; stage Wg packed ----
    #pragma unroll
    for (int ni = 0; ni < 8; ni++) {
        int c = col0 + ni*8 + ctg*2;
        int r1 = row0 + gid;
        R2[r1*132 + c]     = cacc[ni][0];
        R2[r1*132 + c + 1] = cacc[ni][1];
        R2[(r1+8)*132 + c]     = cacc[ni][2];
        R2[(r1+8)*132 + c + 1] = cacc[ni][3];
    }
    stage_weight_packed(ws, Wg, tid);
    __syncthreads();

    // ---- P8: gamma MMA ----
    float gacc[8][4];
    #pragma unroll
    for (int ni = 0; ni < 8; ni++)
        #pragma unroll
        for (int j = 0; j < 4; j++) gacc[ni][j] = 0.f;
    #pragma unroll
    for (int ks = 0; ks < 16; ks++) {
        int k0 = ks * 8;
        const float* rp = R2 + (row0 + gid)*132 + k0 + ctg;
        uint32_t a0 = f2tf32(rp[0]);
        uint32_t a1 = f2tf32(rp[8*132]);
        uint32_t a2 = f2tf32(rp[4]);
        uint32_t a3 = f2tf32(rp[8*132 + 4]);
        #pragma unroll
        for (int ni = 0; ni < 8; ni++) {
            uint2 b2 = BFRAG(ws, nt0 + ni, ks);
            MMA_TF32(gacc[ni], a0, a1, a2, a3, b2.x, b2.y);
        }
    }
    __syncthreads();

    // ---- P9: g_A = sigmoid(ctx)*(gacc+bg); stage Wb packed ----
    #pragma unroll
    for (int ni = 0; ni < 8; ni++) {
        int c = col0 + ni*8 + ctg*2;
        float2 b2 = *(const float2*)&bg[c];
        int r1 = row0 + gid;
        {
            float cx = R2[r1*132 + c], cy = R2[r1*132 + c + 1];
            float2 r2;
            r2.x = (1.f/(1.f+__expf(-cx))) * (gacc[ni][0] + b2.x);
            r2.y = (1.f/(1.f+__expf(-cy))) * (gacc[ni][1] + b2.y);
            *(float2*)&g_A[(t0 + r1)*128 + c] = r2;
        }
        {
            float cx = R2[(r1+8)*132 + c], cy = R2[(r1+8)*132 + c + 1];
            float2 r2;
            r2.x = (1.f/(1.f+__expf(-cx))) * (gacc[ni][2] + b2.x);
            r2.y = (1.f/(1.f+__expf(-cy))) * (gacc[ni][3] + b2.y);
            *(float2*)&g_A[(t0 + r1 + 8)*128 + c] = r2;
        }
    }
    stage_weight_packed(ws, Wb, tid);
    __syncthreads();

    // ---- P10: beta MMA ----
    float bacc[8][4];
    #pragma unroll
    for (int ni = 0; ni < 8; ni++)
        #pragma unroll
        for (int j = 0; j < 4; j++) bacc[ni][j] = 0.f;
    #pragma unroll
    for (int ks = 0; ks < 16; ks++) {
        int k0 = ks * 8;
        const float* rp = R2 + (row0 + gid)*132 + k0 + ctg;
        uint32_t a0 = f2tf32(rp[0]);
        uint32_t a1 = f2tf32(rp[8*132]);
        uint32_t a2 = f2tf32(rp[4]);
        uint32_t a3 = f2tf32(rp[8*132 + 4]);
        #pragma unroll
        for (int ni = 0; ni < 8; ni++) {
            uint2 b2 = BFRAG(ws, nt0 + ni, ks);
            MMA_TF32(bacc[ni], a0, a1, a2, a3, b2.x, b2.y);
        }
    }

    // ---- P11: g_B ----
    #pragma unroll
    for (int ni = 0; ni < 8; ni++) {
        int c = col0 + ni*8 + ctg*2;
        float2 b2 = *(const float2*)&bb[c];
        int r1 = row0 + gid;
        {
            float cx = R2[r1*132 + c], cy = R2[r1*132 + c + 1];
            float2 r2;
            r2.x = (1.f/(1.f+__expf(-cx))) * (bacc[ni][0] + b2.x);
            r2.y = (1.f/(1.f+__expf(-cy))) * (bacc[ni][1] + b2.y);
            *(float2*)&g_B[(t0 + r1)*128 + c] = r2;
        }
        {
            float cx = R2[(r1+8)*132 + c], cy = R2[(r1+8)*132 + c + 1];
            float2 r2;
            r2.x = (1.f/(1.f+__expf(-cx))) * (bacc[ni][2] + b2.x);
            r2.y = (1.f/(1.f+__expf(-cy))) * (bacc[ni][3] + b2.y);
            *(float2*)&g_B[(t0 + r1 + 8)*128 + c] = r2;
        }
    }
}

// ============================================================================
// Kernel 3: final — equi GEMM, R3 structure (proven) + packed We (LDS.64 B).
// 2048 CTAs of 128x128, 2-buffer cp.async k-chunk pipeline.
// smem: packed We 16384 words (64KB) + 2 x A-chunk [128][36] = 100 KB -> 2/SM.
// ============================================================================
#define FK_SMEM ((16384 + 2*128*36) * 4)

__global__ void __launch_bounds__(256, 2)
final_kernel(const float* __restrict__ h_prime,
             const float* __restrict__ We,
             float* __restrict__ out) {
    extern __shared__ uint32_t smu[];
    uint32_t* ws = smu;                          // packed We [16384]
    float* ab0 = (float*)(smu + 16384);
    float* ab1 = (float*)(smu + 16384 + 128*36);

    int tid = threadIdx.x;
    size_t base = (size_t)blockIdx.x * 128;

    stage_weight_packed(ws, We, tid);
    {
        const float* src0 = h_prime + base*128;
        #pragma unroll
        for (int i = tid; i < 1024; i += 256) {
            int r = i >> 3, q = i & 7;
            cp16(&ab0[r*36 + q*4], src0 + (size_t)r*128 + q*4);
        }
        asm volatile("cp.async.commit_group;");
        const float* src1 = h_prime + base*128 + 32;
        #pragma unroll
        for (int i = tid; i < 1024; i += 256) {
            int r = i >> 3, q = i & 7;
            cp16(&ab1[r*36 + q*4], src1 + (size_t)r*128 + q*4);
        }
        asm volatile("cp.async.commit_group;");
    }

    int w = tid >> 5, lane = tid & 31;
    int gid = lane >> 2, ctg = lane & 3;
    int row0 = (w & 3) * 32;
    int col0 = (w >> 2) * 64;
    int nt0  = (w >> 2) * 8;

    float acc[2][8][4];
    #pragma unroll
    for (int mi = 0; mi < 2; mi++)
        #pragma unroll
        for (int ni = 0; ni < 8; ni++)
            #pragma unroll
            for (int j = 0; j < 4; j++) acc[mi][ni][j] = 0.f;

    #pragma unroll
    for (int kc = 0; kc < 4; kc++) {
        if (kc < 3) asm volatile("cp.async.wait_group 1;");
        else        asm volatile("cp.async.wait_group 0;");
        __syncthreads();
        const float* buf = (kc & 1) ? ab1 : ab0;

        #pragma unroll
        for (int ksx = 0; ksx < 4; ksx++) {
            int klo = ksx * 8;
            int ksg = kc*4 + ksx;                // global k-step
            uint32_t a[2][4];
            #pragma unroll
            for (int mi = 0; mi < 2; mi++) {
                const float* rp = buf + (row0 + mi*16 + gid)*36 + klo + ctg;
                a[mi][0] = f2tf32(rp[0]);
                a[mi][1] = f2tf32(rp[8*36]);
                a[mi][2] = f2tf32(rp[4]);
                a[mi][3] = f2tf32(rp[8*36 + 4]);
            }
            #pragma unroll
            for (int ni = 0; ni < 8; ni++) {
                uint2 b2 = BFRAG(ws, nt0 + ni, ksg);
                #pragma unroll
                for (int mi = 0; mi < 2; mi++)
                    MMA_TF32(acc[mi][ni], a[mi][0], a[mi][1], a[mi][2], a[mi][3], b2.x, b2.y);
            }
        }
        __syncthreads();

        if (kc + 2 < 4) {
            float* dstb = (kc & 1) ? ab1 : ab0;
            const float* src = h_prime + base*128 + (kc + 2)*32;
            #pragma unroll
            for (int i = tid; i < 1024; i += 256) {
                int r = i >> 3, q = i & 7;
                cp16(&dstb[r*36 + q*4], src + (size_t)r*128 + q*4);
            }
            asm volatile("cp.async.commit_group;");
        }
    }

    #pragma unroll
    for (int mi = 0; mi < 2; mi++) {
        #pragma unroll
        for (int ni = 0; ni < 8; ni++) {
            int c = col0 + ni*8 + ctg*2;
            {
                size_t R = base + row0 + mi*16 + gid;
                size_t t = R >> 3;
                float2 h2 = *(const float2*)&h_prime[R*128 + c];
                float2 A2 = *(const float2*)&g_A[t*128 + c];
                float2 B2 = *(const float2*)&g_B[t*128 + c];
                float2 r2;
                r2.x = h2.x + A2.x * acc[mi][ni][0] + B2.x;
                r2.y = h2.y + A2.y * acc[mi][ni][1] + B2.y;
                *(float2*)&out[R*128 + c] = r2;
            }
            {
                size_t R = base + row0 + mi*16 + gid + 8;
                size_t t = R >> 3;
                float2 h2 = *(const float2*)&h_prime[R*128 + c];
                float2 A2 = *(const float2*)&g_A[t*128 + c];
                float2 B2 = *(const float2*)&g_B[t*128 + c];
                float2 r2;
                r2.x = h2.x + A2.x * acc[mi][ni][2] + B2.x;
                r2.y = h2.y + A2.y * acc[mi][ni][3] + B2.y;
                *(float2*)&out[R*128 + c] = r2;
            }
        }
    }
}

// ============================================================================
extern "C" void kernel_launch(void* const* d_in, const int* in_sizes, int n_in,
                              void* d_out, int out_size) {
    const float* h_prime = (const float*)d_in[0];
    const float* h_llm   = (const float*)d_in[1];
    const float* Wq = (const float*)d_in[2];
    const float* bq = (const float*)d_in[3];
    const float* Wk = (const float*)d_in[4];
    const float* bk = (const float*)d_in[5];
    const float* Wv = (const float*)d_in[6];
    const float* bv = (const float*)d_in[7];
    const float* Wg = (const float*)d_in[8];
    const float* bg = (const float*)d_in[9];
    const float* Wb = (const float*)d_in[10];
    const float* bb = (const float*)d_in[11];
    const float* We = (const float*)d_in[12];
    float* out = (float*)d_out;

    cudaFuncSetAttribute(kv3_kernel,   cudaFuncAttributeMaxDynamicSharedMemorySize, KV3_SMEM);
    cudaFuncSetAttribute(mega2_kernel, cudaFuncAttributeMaxDynamicSharedMemorySize, M2_SMEM);
    cudaFuncSetAttribute(final_kernel, cudaFuncAttributeMaxDynamicSharedMemorySize, FK_SMEM);

    kv3_kernel<<<128, 256, KV3_SMEM>>>(h_llm, Wk, Wv);
    kv_reduce<<<128, 256>>>(bk, bv);
    mega2_kernel<<<512, 256, M2_SMEM>>>(h_prime, Wq, bq, Wg, bg, Wb, bb);
    final_kernel<<<2048, 256, FK_SMEM>>>(h_prime, We, out);
}

// round 15
// speedup vs baseline: 1.4564x; 1.4564x over previous
#include <cuda_runtime.h>
#include <math.h>
#include <stdint.h>

// Problem constants
#define B_    8
#define NE    4
#define Tn    1024
#define D_    1024
#define G_    8
#define BLK   128
#define TT    64
#define DLLM  2048
#define NT    (B_*NE*Tn)          // 32768 tokens
#define SCALEF 0.08838834764831845f  // 128^-0.5

// -------- device scratch (static, no dynamic allocation) --------
__device__ float g_kvp[8*2*8*64*128];    // K-slice partials
__device__ float g_k[B_*TT*BLK];         // [8][64][128]
__device__ float g_v[B_*TT*BLK];
__device__ float g_A[NT*BLK];            // gate*gamma
__device__ float g_B[NT*BLK];            // gate*beta

__device__ __forceinline__ uint32_t f2tf32(float x) {
    uint32_t u;
    asm("cvt.rna.tf32.f32 %0, %1;" : "=r"(u) : "f"(x));
    return u;
}

__device__ __forceinline__ void cp16(void* dst_smem, const void* src_gmem) {
    uint32_t d = (uint32_t)__cvta_generic_to_shared(dst_smem);
    asm volatile("cp.async.cg.shared.global [%0], [%1], 16;" :: "r"(d), "l"(src_gmem));
}

#define MMA_TF32(acc, a0,a1,a2,a3, b0,b1) \
    asm volatile( \
        "mma.sync.aligned.m16n8k8.row.col.f32.tf32.tf32.f32 " \
        "{%0,%1,%2,%3}, {%4,%5,%6,%7}, {%8,%9}, {%0,%1,%2,%3};" \
        : "+f"(acc[0]), "+f"(acc[1]), "+f"(acc[2]), "+f"(acc[3]) \
        : "r"(a0), "r"(a1), "r"(a2), "r"(a3), "r"(b0), "r"(b1))

// ============================================================================
// Kernel 1: kv3 — split-K tf32 MMA k/v projection (R12, proven).
// ============================================================================
#define KV3_SMEM (2 * (64 + 128) * 68 * 4)

__global__ void __launch_bounds__(256)
kv3_kernel(const float* __restrict__ h_llm,
           const float* __restrict__ Wk,
           const float* __restrict__ Wv) {
    extern __shared__ float sm[];
    float* ab[2] = { sm,                sm + 64*68 };
    float* wb[2] = { sm + 2*64*68,      sm + 2*64*68 + 128*68 };

    int tid = threadIdx.x;
    int bid = blockIdx.x;
    int slice = bid >> 4;
    int b     = (bid >> 1) & 7;
    int which = bid & 1;
    const float* W    = which ? Wv : Wk;
    const float* hsrc = h_llm + (size_t)b * TT * DLLM + slice * 256;
    const float* wsrc = W + slice * 256;

    auto issue = [&](int ch, int bi) {
        const float* as = hsrc + ch * 64;
        const float* bs = wsrc + ch * 64;
        #pragma unroll
        for (int i = tid; i < 1024; i += 256) {
            int r = i >> 4, q = i & 15;
            cp16(&ab[bi][r*68 + q*4], as + (size_t)r*DLLM + q*4);
        }
        #pragma unroll
        for (int i = tid; i < 2048; i += 256) {
            int r = i >> 4, q = i & 15;
            cp16(&wb[bi][r*68 + q*4], bs + (size_t)r*DLLM + q*4);
        }
        asm volatile("cp.async.commit_group;");
    };

    issue(0, 0);
    issue(1, 1);

    int w = tid >> 5, lane = tid & 31;
    int gid = lane >> 2, ctg = lane & 3;
    int row0 = (w & 3) * 16;
    int col0 = (w >> 2) * 64;

    float acc[8][4];
    #pragma unroll
    for (int ni = 0; ni < 8; ni++)
        #pragma unroll
        for (int j = 0; j < 4; j++) acc[ni][j] = 0.f;

    #pragma unroll
    for (int ch = 0; ch < 4; ch++) {
        if (ch == 3) asm volatile("cp.async.wait_group 0;");
        else         asm volatile("cp.async.wait_group 1;");
        __syncthreads();
        const float* A  = ab[ch & 1];
        const float* Wf = wb[ch & 1];

        #pragma unroll
        for (int ks = 0; ks < 8; ks++) {
            int k0 = ks * 8;
            const float* rp = A + (row0 + gid)*68 + k0 + ctg;
            uint32_t a0 = f2tf32(rp[0]);
            uint32_t a1 = f2tf32(rp[8*68]);
            uint32_t a2 = f2tf32(rp[4]);
            uint32_t a3 = f2tf32(rp[8*68 + 4]);
            #pragma unroll
            for (int ni = 0; ni < 8; ni++) {
                const float* np = Wf + (col0 + ni*8 + gid)*68 + k0 + ctg;
                uint32_t b0 = f2tf32(np[0]);
                uint32_t b1 = f2tf32(np[4]);
                MMA_TF32(acc[ni], a0, a1, a2, a3, b0, b1);
            }
        }
        __syncthreads();
        if (ch + 2 < 4) issue(ch + 2, ch & 1);
    }

    float* outp = g_kvp + ((size_t)(slice*2 + which)*8 + b) * 8192;
    #pragma unroll
    for (int ni = 0; ni < 8; ni++) {
        int o = col0 + ni*8 + ctg*2;
        int s1 = row0 + gid;
        *(float2*)&outp[s1*128 + o]     = make_float2(acc[ni][0], acc[ni][1]);
        *(float2*)&outp[(s1+8)*128 + o] = make_float2(acc[ni][2], acc[ni][3]);
    }
}

__global__ void kv_reduce(const float* __restrict__ bk,
                          const float* __restrict__ bv) {
    int idx = blockIdx.x * 256 + threadIdx.x;
    if (idx >= 2*8*64*128/4) return;
    int which = idx >> 14;
    int rem   = idx & 16383;
    int o4 = rem & 31;
    const float* bias = which ? bv : bk;
    float4 s = *(const float4*)&bias[o4*4];
    #pragma unroll
    for (int sl = 0; sl < 8; sl++) {
        const float4* p = (const float4*)(g_kvp + (size_t)(sl*2 + which)*65536) + rem;
        float4 v = *p;
        s.x += v.x; s.y += v.y; s.z += v.z; s.w += v.w;
    }
    float* dst = which ? g_v : g_k;
    *((float4*)dst + rem) = s;
}

// ============================================================================
// Kernel 2: mega2 — fused maxpool -> q -> attention -> gamma/beta (R12, proven).
// ============================================================================
#define M2_SMEM (25600 * 4)

__global__ void __launch_bounds__(256)
mega2_kernel(const float* __restrict__ h_prime,
             const float* __restrict__ Wq, const float* __restrict__ bq,
             const float* __restrict__ Wg, const float* __restrict__ bg,
             const float* __restrict__ Wb, const float* __restrict__ bb) {
    extern __shared__ float smf[];
    float* R1 = smf;                 // 17152 floats
    float* R2 = smf + 17152;         // 8448: inv -> q -> ctx, stride 132
    uint32_t* ws = (uint32_t*)R1;    // weight view (tf32), [128][132]
    float* kbuf = R1;                // k [64][132]
    float* vbuf = R1 + 8448;         // vT [128][68]
    float* ss   = R1;                // scores [64][68]

    int tid = threadIdx.x;
    size_t t0 = (size_t)blockIdx.x * 64;
    int b = (int)(t0 >> 12);

    int w = tid >> 5, lane = tid & 31;
    int gid = lane >> 2, ctg = lane & 3;
    int row0  = (w & 3) * 16;
    int col0  = (w >> 2) * 64;
    int col0s = (w >> 2) * 32;

    // ---- P0: stage Wq (tf32) + maxpool inv -> R2 ----
    {
        const float4* wsrc = (const float4*)Wq;
        #pragma unroll 4
        for (int i4 = tid; i4 < 4096; i4 += 256) {
            float4 v = wsrc[i4];
            int idx = i4 * 4;
            int r = idx >> 7, k = idx & 127;
            uint32_t* p = &ws[r*132 + k];
            p[0] = f2tf32(v.x); p[1] = f2tf32(v.y); p[2] = f2tf32(v.z); p[3] = f2tf32(v.w);
        }
        #pragma unroll 2
        for (int i4 = tid; i4 < 2048; i4 += 256) {
            int t = i4 >> 5, d4 = i4 & 31;
            const float4* hp = (const float4*)(h_prime + (t0 + t)*1024 + d4*4);
            float4 m = hp[0];
            #pragma unroll
            for (int g = 1; g < 8; g++) {
                float4 x = hp[g*32];
                m.x = fmaxf(m.x, x.x); m.y = fmaxf(m.y, x.y);
                m.z = fmaxf(m.z, x.z); m.w = fmaxf(m.w, x.w);
            }
            *(float4*)&R2[t*132 + d4*4] = m;
        }
    }
    __syncthreads();

    // ---- P1: q = inv @ WqT ----
    float qacc[8][4];
    #pragma unroll
    for (int ni = 0; ni < 8; ni++)
        #pragma unroll
        for (int j = 0; j < 4; j++) qacc[ni][j] = 0.f;
    #pragma unroll
    for (int ks = 0; ks < 16; ks++) {
        int k0 = ks * 8;
        const float* rp = R2 + (row0 + gid)*132 + k0 + ctg;
        uint32_t a0 = f2tf32(rp[0]);
        uint32_t a1 = f2tf32(rp[8*132]);
        uint32_t a2 = f2tf32(rp[4]);
        uint32_t a3 = f2tf32(rp[8*132 + 4]);
        #pragma unroll
        for (int ni = 0; ni < 8; ni++) {
            int nb = (col0 + ni*8 + gid) * 132;
            uint32_t b0 = ws[nb + k0 + ctg];
            uint32_t b1 = ws[nb + k0 + ctg + 4];
            MMA_TF32(qacc[ni], a0, a1, a2, a3, b0, b1);
        }
    }
    __syncthreads();

    // ---- P2: write q (scaled+biased) over inv; load k + vT ----
    #pragma unroll
    for (int ni = 0; ni < 8; ni++) {
        int c = col0 + ni*8 + ctg*2;
        float2 b2 = *(const float2*)&bq[c];
        int r1 = row0 + gid;
        R2[r1*132 + c]     = (qacc[ni][0] + b2.x) * SCALEF;
        R2[r1*132 + c + 1] = (qacc[ni][1] + b2.y) * SCALEF;
        R2[(r1+8)*132 + c]     = (qacc[ni][2] + b2.x) * SCALEF;
        R2[(r1+8)*132 + c + 1] = (qacc[ni][3] + b2.y) * SCALEF;
    }
    for (int i4 = tid; i4 < 2048; i4 += 256) {
        int s = i4 >> 5, d4 = i4 & 31;
        *(float4*)&kbuf[s*132 + d4*4] = *(const float4*)&g_k[(size_t)b*8192 + s*128 + d4*4];
    }
    for (int idx = tid; idx < 8192; idx += 256) {
        int s = idx >> 7, d = idx & 127;
        vbuf[d*68 + s] = g_v[(size_t)b*8192 + idx];
    }
    __syncthreads();

    // ---- P3: scores = q @ kT ----
    float sacc[4][4];
    #pragma unroll
    for (int ni = 0; ni < 4; ni++)
        #pragma unroll
        for (int j = 0; j < 4; j++) sacc[ni][j] = 0.f;
    #pragma unroll
    for (int ks = 0; ks < 16; ks++) {
        int k0 = ks * 8;
        const float* rp = R2 + (row0 + gid)*132 + k0 + ctg;
        uint32_t a0 = f2tf32(rp[0]);
        uint32_t a1 = f2tf32(rp[8*132]);
        uint32_t a2 = f2tf32(rp[4]);
        uint32_t a3 = f2tf32(rp[8*132 + 4]);
        #pragma unroll
        for (int ni = 0; ni < 4; ni++) {
            const float* np = kbuf + (col0s + ni*8 + gid)*132 + k0 + ctg;
            uint32_t b0 = f2tf32(np[0]);
            uint32_t b1 = f2tf32(np[4]);
            MMA_TF32(sacc[ni], a0, a1, a2, a3, b0, b1);
        }
    }
    __syncthreads();

    // ---- P4: write scores (stride 68) ----
    #pragma unroll
    for (int ni = 0; ni < 4; ni++) {
        int c = col0s + ni*8 + ctg*2;
        int r1 = row0 + gid;
        ss[r1*68 + c]     = sacc[ni][0];
        ss[r1*68 + c + 1] = sacc[ni][1];
        ss[(r1+8)*68 + c]     = sacc[ni][2];
        ss[(r1+8)*68 + c + 1] = sacc[ni][3];
    }
    __syncthreads();

    // ---- P5: softmax ----
    if (tid < 64) {
        float* row = ss + tid*68;
        float m = row[0];
        #pragma unroll 8
        for (int s = 1; s < 64; s++) m = fmaxf(m, row[s]);
        float sum = 0.f;
        #pragma unroll 8
        for (int s = 0; s < 64; s++) { float e = __expf(row[s] - m); row[s] = e; sum += e; }
        float inv = 1.f / sum;
        #pragma unroll 8
        for (int s = 0; s < 64; s++) row[s] *= inv;
    }
    __syncthreads();

    // ---- P6: ctx = attn @ v ----
    float cacc[8][4];
    #pragma unroll
    for (int ni = 0; ni < 8; ni++)
        #pragma unroll
        for (int j = 0; j < 4; j++) cacc[ni][j] = 0.f;
    #pragma unroll
    for (int ks = 0; ks < 8; ks++) {
        int k0 = ks * 8;
        const float* rp = ss + (row0 + gid)*68 + k0 + ctg;
        uint32_t a0 = f2tf32(rp[0]);
        uint32_t a1 = f2tf32(rp[8*68]);
        uint32_t a2 = f2tf32(rp[4]);
        uint32_t a3 = f2tf32(rp[8*68 + 4]);
        #pragma unroll
        for (int ni = 0; ni < 8; ni++) {
            const float* np = vbuf + (col0 + ni*8 + gid)*68 + k0 + ctg;
            uint32_t b0 = f2tf32(np[0]);
            uint32_t b1 = f2tf32(np[4]);
            MMA_TF32(cacc[ni], a0, a1, a2, a3, b0, b1);
        }
    }
    __syncthreads();

    // ---- P7: write ctx over q; stage Wg ----
    #pragma unroll
    for (int ni = 0; ni < 8; ni++) {
        int c = col0 + ni*8 + ctg*2;
        int r1 = row0 + gid;
        R2[r1*132 + c]     = cacc[ni][0];
        R2[r1*132 + c + 1] = cacc[ni][1];
        R2[(r1+8)*132 + c]     = cacc[ni][2];
        R2[(r1+8)*132 + c + 1] = cacc[ni][3];
    }
    {
        const float4* wsrc = (const float4*)Wg;
        #pragma unroll 4
        for (int i4 = tid; i4 < 4096; i4 += 256) {
            float4 v = wsrc[i4];
            int idx = i4 * 4;
            int r = idx >> 7, k = idx & 127;
            uint32_t* p = &ws[r*132 + k];
            p[0] = f2tf32(v.x); p[1] = f2tf32(v.y); p[2] = f2tf32(v.z); p[3] = f2tf32(v.w);
        }
    }
    __syncthreads();

    // ---- P8: gamma MMA ----
    float gacc[8][4];
    #pragma unroll
    for (int ni = 0; ni < 8; ni++)
        #pragma unroll
        for (int j = 0; j < 4; j++) gacc[ni][j] = 0.f;
    #pragma unroll
    for (int ks = 0; ks < 16; ks++) {
        int k0 = ks * 8;
        const float* rp = R2 + (row0 + gid)*132 + k0 + ctg;
        uint32_t a0 = f2tf32(rp[0]);
        uint32_t a1 = f2tf32(rp[8*132]);
        uint32_t a2 = f2tf32(rp[4]);
        uint32_t a3 = f2tf32(rp[8*132 + 4]);
        #pragma unroll
        for (int ni = 0; ni < 8; ni++) {
            int nb = (col0 + ni*8 + gid) * 132;
            uint32_t b0 = ws[nb + k0 + ctg];
            uint32_t b1 = ws[nb + k0 + ctg + 4];
            MMA_TF32(gacc[ni], a0, a1, a2, a3, b0, b1);
        }
    }
    __syncthreads();

    // ---- P9: g_A = sigmoid(ctx)*(gacc+bg); stage Wb ----
    #pragma unroll
    for (int ni = 0; ni < 8; ni++) {
        int c = col0 + ni*8 + ctg*2;
        float2 b2 = *(const float2*)&bg[c];
        int r1 = row0 + gid;
        {
            float cx = R2[r1*132 + c], cy = R2[r1*132 + c + 1];
            float2 r2;
            r2.x = (1.f/(1.f+__expf(-cx))) * (gacc[ni][0] + b2.x);
            r2.y = (1.f/(1.f+__expf(-cy))) * (gacc[ni][1] + b2.y);
            *(float2*)&g_A[(t0 + r1)*128 + c] = r2;
        }
        {
            float cx = R2[(r1+8)*132 + c], cy = R2[(r1+8)*132 + c + 1];
            float2 r2;
            r2.x = (1.f/(1.f+__expf(-cx))) * (gacc[ni][2] + b2.x);
            r2.y = (1.f/(1.f+__expf(-cy))) * (gacc[ni][3] + b2.y);
            *(float2*)&g_A[(t0 + r1 + 8)*128 + c] = r2;
        }
    }
    {
        const float4* wsrc = (const float4*)Wb;
        #pragma unroll 4
        for (int i4 = tid; i4 < 4096; i4 += 256) {
            float4 v = wsrc[i4];
            int idx = i4 * 4;
            int r = idx >> 7, k = idx & 127;
            uint32_t* p = &ws[r*132 + k];
            p[0] = f2tf32(v.x); p[1] = f2tf32(v.y); p[2] = f2tf32(v.z); p[3] = f2tf32(v.w);
        }
    }
    __syncthreads();

    // ---- P10: beta MMA ----
    float bacc[8][4];
    #pragma unroll
    for (int ni = 0; ni < 8; ni++)
        #pragma unroll
        for (int j = 0; j < 4; j++) bacc[ni][j] = 0.f;
    #pragma unroll
    for (int ks = 0; ks < 16; ks++) {
        int k0 = ks * 8;
        const float* rp = R2 + (row0 + gid)*132 + k0 + ctg;
        uint32_t a0 = f2tf32(rp[0]);
        uint32_t a1 = f2tf32(rp[8*132]);
        uint32_t a2 = f2tf32(rp[4]);
        uint32_t a3 = f2tf32(rp[8*132 + 4]);
        #pragma unroll
        for (int ni = 0; ni < 8; ni++) {
            int nb = (col0 + ni*8 + gid) * 132;
            uint32_t b0 = ws[nb + k0 + ctg];
            uint32_t b1 = ws[nb + k0 + ctg + 4];
            MMA_TF32(bacc[ni], a0, a1, a2, a3, b0, b1);
        }
    }

    // ---- P11: g_B ----
    #pragma unroll
    for (int ni = 0; ni < 8; ni++) {
        int c = col0 + ni*8 + ctg*2;
        float2 b2 = *(const float2*)&bb[c];
        int r1 = row0 + gid;
        {
            float cx = R2[r1*132 + c], cy = R2[r1*132 + c + 1];
            float2 r2;
            r2.x = (1.f/(1.f+__expf(-cx))) * (bacc[ni][0] + b2.x);
            r2.y = (1.f/(1.f+__expf(-cy))) * (bacc[ni][1] + b2.y);
            *(float2*)&g_B[(t0 + r1)*128 + c] = r2;
        }
        {
            float cx = R2[(r1+8)*132 + c], cy = R2[(r1+8)*132 + c + 1];
            float2 r2;
            r2.x = (1.f/(1.f+__expf(-cx))) * (bacc[ni][2] + b2.x);
            r2.y = (1.f/(1.f+__expf(-cy))) * (bacc[ni][3] + b2.y);
            *(float2*)&g_B[(t0 + r1 + 8)*128 + c] = r2;
        }
    }
}

// ============================================================================
// Kernel 3: final — equi GEMM, R3/R12 mainloop (proven, untouched) +
// NEW: at kc==2, prefetch this CTA's g_A/g_B tiles via cp.async into the
// dead ab0 buffer; epilogue reads A/B from smem (tail gmem latency hidden
// behind kc=3's compute).
// ============================================================================
#define FK_SMEM ((16896 + 2*128*36) * 4)

__global__ void __launch_bounds__(256, 2)
final_kernel(const float* __restrict__ h_prime,
             const float* __restrict__ We,
             float* __restrict__ out) {
    extern __shared__ uint32_t smu[];
    uint32_t* ws = smu;
    float* ab0 = (float*)(smu + 16896);
    float* ab1 = (float*)(smu + 16896 + 128*36);

    int tid = threadIdx.x;
    size_t base = (size_t)blockIdx.x * 128;

    const float4* wsrc = (const float4*)We;
    #pragma unroll 4
    for (int i4 = tid; i4 < 4096; i4 += 256) {
        float4 v = wsrc[i4];
        int idx = i4 * 4;
        int r = idx >> 7, k = idx & 127;
        uint32_t* p = &ws[r*132 + k];
        p[0] = f2tf32(v.x); p[1] = f2tf32(v.y); p[2] = f2tf32(v.z); p[3] = f2tf32(v.w);
    }
    {
        const float* src0 = h_prime + base*128;
        #pragma unroll
        for (int i = tid; i < 1024; i += 256) {
            int r = i >> 3, q = i & 7;
            cp16(&ab0[r*36 + q*4], src0 + (size_t)r*128 + q*4);
        }
        asm volatile("cp.async.commit_group;");
        const float* src1 = h_prime + base*128 + 32;
        #pragma unroll
        for (int i = tid; i < 1024; i += 256) {
            int r = i >> 3, q = i & 7;
            cp16(&ab1[r*36 + q*4], src1 + (size_t)r*128 + q*4);
        }
        asm volatile("cp.async.commit_group;");
    }

    int w = tid >> 5, lane = tid & 31;
    int gid = lane >> 2, ctg = lane & 3;
    int row0 = (w & 3) * 32;
    int col0 = (w >> 2) * 64;

    float acc[2][8][4];
    #pragma unroll
    for (int mi = 0; mi < 2; mi++)
        #pragma unroll
        for (int ni = 0; ni < 8; ni++)
            #pragma unroll
            for (int j = 0; j < 4; j++) acc[mi][ni][j] = 0.f;

    #pragma unroll
    for (int kc = 0; kc < 4; kc++) {
        // With the extra gA/gB group issued at kc==2, "1 group outstanding"
        // is correct for every iteration (own chunk always complete).
        asm volatile("cp.async.wait_group 1;");
        __syncthreads();
        const float* buf = (kc & 1) ? ab1 : ab0;

        #pragma unroll
        for (int ksx = 0; ksx < 4; ksx++) {
            int klo = ksx * 8;
            uint32_t a[2][4];
            #pragma unroll
            for (int mi = 0; mi < 2; mi++) {
                const float* rp = buf + (row0 + mi*16 + gid)*36 + klo + ctg;
                a[mi][0] = f2tf32(rp[0]);
                a[mi][1] = f2tf32(rp[8*36]);
                a[mi][2] = f2tf32(rp[4]);
                a[mi][3] = f2tf32(rp[8*36 + 4]);
            }
            int kg = kc*32 + klo;
            #pragma unroll
            for (int ni = 0; ni < 8; ni++) {
                int nb = (col0 + ni*8 + gid) * 132;
                uint32_t b0 = ws[nb + kg + ctg];
                uint32_t b1 = ws[nb + kg + ctg + 4];
                #pragma unroll
                for (int mi = 0; mi < 2; mi++)
                    MMA_TF32(acc[mi][ni], a[mi][0], a[mi][1], a[mi][2], a[mi][3], b0, b1);
            }
        }
        __syncthreads();

        if (kc + 2 < 4) {
            // refill the just-freed buffer with chunk kc+2
            float* dstb = (kc & 1) ? ab1 : ab0;
            const float* src = h_prime + base*128 + (kc + 2)*32;
            #pragma unroll
            for (int i = tid; i < 1024; i += 256) {
                int r = i >> 3, q = i & 7;
                cp16(&dstb[r*36 + q*4], src + (size_t)r*128 + q*4);
            }
            asm volatile("cp.async.commit_group;");
        } else if (kc == 2) {
            // ab0 is dead: prefetch g_A (8KB) + g_B (8KB) tiles into it,
            // overlapping with kc=3's compute on ab1.
            const float* srcA = g_A + (base >> 3) * 128;   // 2048 floats
            const float* srcB = g_B + (base >> 3) * 128;
            #pragma unroll
            for (int i = tid; i < 512; i += 256)
                cp16(&ab0[i*4], srcA + i*4);
            #pragma unroll
            for (int i = tid; i < 512; i += 256)
                cp16(&ab0[2048 + i*4], srcB + i*4);
            asm volatile("cp.async.commit_group;");
        }
    }

    // drain the gA/gB prefetch group, then epilogue from smem
    asm volatile("cp.async.wait_group 0;");
    __syncthreads();
    const float* gAs = ab0;          // [16 tokens][128]
    const float* gBs = ab0 + 2048;

    #pragma unroll
    for (int mi = 0; mi < 2; mi++) {
        #pragma unroll
        for (int ni = 0; ni < 8; ni++) {
            int c = col0 + ni*8 + ctg*2;
            {
                int r_l = row0 + mi*16 + gid;
                size_t R = base + r_l;
                int tl = r_l >> 3;
                float2 h2 = *(const float2*)&h_prime[R*128 + c];
                float2 A2 = *(const float2*)&gAs[tl*128 + c];
                float2 B2 = *(const float2*)&gBs[tl*128 + c];
                float2 r2;
                r2.x = h2.x + A2.x * acc[mi][ni][0] + B2.x;
                r2.y = h2.y + A2.y * acc[mi][ni][1] + B2.y;
                *(float2*)&out[R*128 + c] = r2;
            }
            {
                int r_l = row0 + mi*16 + gid + 8;
                size_t R = base + r_l;
                int tl = r_l >> 3;
                float2 h2 = *(const float2*)&h_prime[R*128 + c];
                float2 A2 = *(const float2*)&gAs[tl*128 + c];
                float2 B2 = *(const float2*)&gBs[tl*128 + c];
                float2 r2;
                r2.x = h2.x + A2.x * acc[mi][ni][2] + B2.x;
                r2.y = h2.y + A2.y * acc[mi][ni][3] + B2.y;
                *(float2*)&out[R*128 + c] = r2;
            }
        }
    }
}

// ============================================================================
extern "C" void kernel_launch(void* const* d_in, const int* in_sizes, int n_in,
                              void* d_out, int out_size) {
    const float* h_prime = (const float*)d_in[0];
    const float* h_llm   = (const float*)d_in[1];
    const float* Wq = (const float*)d_in[2];
    const float* bq = (const float*)d_in[3];
    const float* Wk = (const float*)d_in[4];
    const float* bk = (const float*)d_in[5];
    const float* Wv = (const float*)d_in[6];
    const float* bv = (const float*)d_in[7];
    const float* Wg = (const float*)d_in[8];
    const float* bg = (const float*)d_in[9];
    const float* Wb = (const float*)d_in[10];
    const float* bb = (const float*)d_in[11];
    const float* We = (const float*)d_in[12];
    float* out = (float*)d_out;

    cudaFuncSetAttribute(kv3_kernel,   cudaFuncAttributeMaxDynamicSharedMemorySize, KV3_SMEM);
    cudaFuncSetAttribute(mega2_kernel, cudaFuncAttributeMaxDynamicSharedMemorySize, M2_SMEM);
    cudaFuncSetAttribute(final_kernel, cudaFuncAttributeMaxDynamicSharedMemorySize, FK_SMEM);

    kv3_kernel<<<128, 256, KV3_SMEM>>>(h_llm, Wk, Wv);
    kv_reduce<<<128, 256>>>(bk, bv);
    mega2_kernel<<<512, 256, M2_SMEM>>>(h_prime, Wq, bq, Wg, bg, Wb, bb);
    final_kernel<<<2048, 256, FK_SMEM>>>(h_prime, We, out);
}